// round 3
// baseline (speedup 1.0000x reference)
#include <cuda_runtime.h>
#include <math.h>

#define TT 2048
#define CC 512
#define BB 4

// Scratch (static device arrays — no allocation allowed)
__device__ float g_qkv[BB * 3 * CC * TT];  // qkv projections [B,3C,T]
__device__ float g_att[BB * CC * TT];      // attention output [B,C,T]
__device__ float g_scale[BB * CC];         // fused GN: per (b,c) scale
__device__ float g_shift[BB * CC];         // fused GN: per (b,c) shift

// ---------------------------------------------------------------------------
// GroupNorm statistics: one block per (batch, group). Emits per-channel
// affine (scale, shift) so normalization fuses into the QKV GEMM B-load.
// ---------------------------------------------------------------------------
__global__ void __launch_bounds__(256) gn_stats_kernel(const float* __restrict__ x,
                                                       const float* __restrict__ gamma,
                                                       const float* __restrict__ beta) {
    int bg = blockIdx.x;
    int b = bg >> 5, g = bg & 31;
    const float* xp = x + ((size_t)b * CC + g * 16) * TT;
    int tid = threadIdx.x;

    const int N4 = 16 * TT / 4;  // 8192 float4
    const float4* x4 = (const float4*)xp;
    float s = 0.f, s2 = 0.f;
    for (int i = tid; i < N4; i += 256) {
        float4 v = x4[i];
        s += v.x + v.y + v.z + v.w;
        s2 += v.x * v.x + v.y * v.y + v.z * v.z + v.w * v.w;
    }
#pragma unroll
    for (int o = 16; o; o >>= 1) {
        s += __shfl_xor_sync(~0u, s, o);
        s2 += __shfl_xor_sync(~0u, s2, o);
    }
    __shared__ float rs[8], rs2[8];
    __shared__ float smean, srinv;
    int w = tid >> 5;
    if ((tid & 31) == 0) { rs[w] = s; rs2[w] = s2; }
    __syncthreads();
    if (tid == 0) {
        float S = 0.f, S2 = 0.f;
        for (int i = 0; i < 8; i++) { S += rs[i]; S2 += rs2[i]; }
        const float invn = 1.f / (16.f * TT);
        float mean = S * invn;
        float var = S2 * invn - mean * mean;
        smean = mean;
        srinv = rsqrtf(var + 1e-5f);
    }
    __syncthreads();
    if (tid < 16) {
        int c = g * 16 + tid;
        float ga = gamma[c] * srinv;
        g_scale[b * CC + c] = ga;
        g_shift[b * CC + c] = beta[c] - smean * ga;
    }
}

// ---------------------------------------------------------------------------
// Tiled SGEMM: C[z] = A[M,K] * B[z][K,N] + bias[M] (+ res[z]).
// BM=BN=128, BK=16; 256 threads; 8x8 micro-tile (all inner loads LDS.128).
// Software-pipelined: next k-tile's LDGs issue right after the smem publish,
// hidden under the current tile's FFMA block.
// GN=true applies per-row (channel) affine to B elements on load.
// ---------------------------------------------------------------------------
template <bool RES, bool GN>
__global__ void __launch_bounds__(256, 2) gemm128(const float* __restrict__ A,
                                                  const float* __restrict__ Bm,
                                                  const float* __restrict__ bias,
                                                  const float* __restrict__ res,
                                                  float* __restrict__ Cm,
                                                  int M, int N, int K) {
    int z = blockIdx.z;
    Bm += (size_t)z * K * N;
    Cm += (size_t)z * M * N;
    if (RES) res += (size_t)z * M * N;
    int m0 = blockIdx.y * 128, n0 = blockIdx.x * 128;

    __shared__ float As[16][132];  // k-major transposed A tile
    __shared__ float Bs[16][128];

    int tid = threadIdx.x;
    int tx = tid & 15, ty = tid >> 4;
    int ar = tid >> 2, akc = (tid & 3) * 4;      // A: rows ar, ar+64; k-chunk akc
    int brow = tid >> 5, bcol = (tid & 31) * 4;  // B: rows brow, brow+8

    const float* Ap0 = A + (size_t)(m0 + ar) * K + akc;
    const float* Ap1 = A + (size_t)(m0 + ar + 64) * K + akc;
    const float* Bp0 = Bm + (size_t)brow * N + n0 + bcol;
    const float* Bp1 = Bm + (size_t)(brow + 8) * N + n0 + bcol;

    float acc[8][8] = {};
    float4 a0, a1, b0, b1;

    // Prologue: load tile k0 = 0
    a0 = *(const float4*)(Ap0);
    a1 = *(const float4*)(Ap1);
    b0 = *(const float4*)(Bp0);
    b1 = *(const float4*)(Bp1);
    if (GN) {
        float ga0 = g_scale[z * CC + brow], be0 = g_shift[z * CC + brow];
        float ga1 = g_scale[z * CC + brow + 8], be1 = g_shift[z * CC + brow + 8];
        b0.x = b0.x * ga0 + be0; b0.y = b0.y * ga0 + be0;
        b0.z = b0.z * ga0 + be0; b0.w = b0.w * ga0 + be0;
        b1.x = b1.x * ga1 + be1; b1.y = b1.y * ga1 + be1;
        b1.z = b1.z * ga1 + be1; b1.w = b1.w * ga1 + be1;
    }

    for (int k0 = 0; k0 < K; k0 += 16) {
        __syncthreads();  // previous tile's compute done; smem free
        As[akc + 0][ar] = a0.x; As[akc + 1][ar] = a0.y;
        As[akc + 2][ar] = a0.z; As[akc + 3][ar] = a0.w;
        As[akc + 0][ar + 64] = a1.x; As[akc + 1][ar + 64] = a1.y;
        As[akc + 2][ar + 64] = a1.z; As[akc + 3][ar + 64] = a1.w;
        *(float4*)&Bs[brow][bcol] = b0;
        *(float4*)&Bs[brow + 8][bcol] = b1;
        __syncthreads();

        // Prefetch next tile (LDGs hidden under the FFMA block below)
        int kn = k0 + 16;
        if (kn < K) {
            a0 = *(const float4*)(Ap0 + kn);
            a1 = *(const float4*)(Ap1 + kn);
            b0 = *(const float4*)(Bp0 + (size_t)kn * N);
            b1 = *(const float4*)(Bp1 + (size_t)kn * N);
            if (GN) {
                float ga0 = g_scale[z * CC + kn + brow];
                float be0 = g_shift[z * CC + kn + brow];
                float ga1 = g_scale[z * CC + kn + brow + 8];
                float be1 = g_shift[z * CC + kn + brow + 8];
                b0.x = b0.x * ga0 + be0; b0.y = b0.y * ga0 + be0;
                b0.z = b0.z * ga0 + be0; b0.w = b0.w * ga0 + be0;
                b1.x = b1.x * ga1 + be1; b1.y = b1.y * ga1 + be1;
                b1.z = b1.z * ga1 + be1; b1.w = b1.w * ga1 + be1;
            }
        }

#pragma unroll
        for (int kk = 0; kk < 16; kk++) {
            float4 xa0 = *(float4*)&As[kk][ty * 8];
            float4 xa1 = *(float4*)&As[kk][ty * 8 + 4];
            float4 yb0 = *(float4*)&Bs[kk][tx * 8];
            float4 yb1 = *(float4*)&Bs[kk][tx * 8 + 4];
            float av[8] = {xa0.x, xa0.y, xa0.z, xa0.w, xa1.x, xa1.y, xa1.z, xa1.w};
            float bv[8] = {yb0.x, yb0.y, yb0.z, yb0.w, yb1.x, yb1.y, yb1.z, yb1.w};
#pragma unroll
            for (int i = 0; i < 8; i++)
#pragma unroll
                for (int j = 0; j < 8; j++) acc[i][j] += av[i] * bv[j];
        }
    }

#pragma unroll
    for (int i = 0; i < 8; i++) {
        int m = m0 + ty * 8 + i;
        float bi = bias[m];
        float4 c0, c1;
        c0.x = acc[i][0] + bi; c0.y = acc[i][1] + bi;
        c0.z = acc[i][2] + bi; c0.w = acc[i][3] + bi;
        c1.x = acc[i][4] + bi; c1.y = acc[i][5] + bi;
        c1.z = acc[i][6] + bi; c1.w = acc[i][7] + bi;
        size_t off = (size_t)m * N + n0 + tx * 8;
        if (RES) {
            float4 r0 = *(const float4*)(res + off);
            float4 r1 = *(const float4*)(res + off + 4);
            c0.x += r0.x; c0.y += r0.y; c0.z += r0.z; c0.w += r0.w;
            c1.x += r1.x; c1.y += r1.y; c1.z += r1.z; c1.w += r1.w;
        }
        *(float4*)(Cm + off) = c0;
        *(float4*)(Cm + off + 4) = c1;
    }
}

// ---------------------------------------------------------------------------
// Flash attention, fp32. One block per (b,h, 64-query tile). 128 threads,
// 8x4 micro-tile: rows r = 8*ty+i (consecutive, float4-loadable),
// cols s/d = tx + 16*j (reduction index warp-uniform -> conflict-free LDS).
// Qs/Ps stride 68 (float4 aligned); Ks/Vs stride 65 (scalar loads).
// ---------------------------------------------------------------------------
__global__ void __launch_bounds__(128, 3) attn_kernel() {
    extern __shared__ float sm[];
    float* Qs = sm;                 // [64][68]  Qs[d*68 + r]
    float* Ps = sm + 64 * 68;       // [64][68]  Ps[s*68 + r]; reused as Os[d*68+r]
    float* Ks = sm + 2 * 64 * 68;   // [64][65]  Ks[d*65 + s]
    float* Vs = Ks + 64 * 65;       // [64][65]  Vs[d*65 + s]

    int bh = blockIdx.y;
    int b = bh >> 3, h = bh & 7;
    int t0 = blockIdx.x * 64;
    const float* qp = g_qkv + ((size_t)b * 1536 + h * 192) * TT + t0;
    const float* kp = g_qkv + ((size_t)b * 1536 + h * 192 + 64) * TT;
    const float* vp = kp + (size_t)64 * TT;

    int tid = threadIdx.x;
    int tx = tid & 15, ty = tid >> 4;  // ty 0..7
    int r0 = ty * 8;

    // Q tile, pre-scaled by 1/sqrt(dh) = 0.125 (= product of reference scales)
    for (int i = tid; i < 4096; i += 128) {
        int d = i >> 6, r = i & 63;
        Qs[d * 68 + r] = qp[(size_t)d * TT + r] * 0.125f;
    }

    float acc[8][4] = {};
    float mrow[8], lrow[8] = {};
#pragma unroll
    for (int i = 0; i < 8; i++) mrow[i] = -1e30f;

    for (int kt = 0; kt < 32; kt++) {
        const float* kpt = kp + kt * 64;
        const float* vpt = vp + kt * 64;
        __syncthreads();
        for (int i = tid; i < 4096; i += 128) {
            int d = i >> 6, s = i & 63;
            Ks[d * 65 + s] = kpt[(size_t)d * TT + s];
            Vs[d * 65 + s] = vpt[(size_t)d * TT + s];
        }
        __syncthreads();

        // S = Q K^T   (S[r][s]: r = 8ty+i, s = tx+16j)
        float S[8][4] = {};
#pragma unroll 4
        for (int d = 0; d < 64; d++) {
            float4 a0 = *(float4*)&Qs[d * 68 + r0];
            float4 a1 = *(float4*)&Qs[d * 68 + r0 + 4];
            float b0 = Ks[d * 65 + tx];
            float b1 = Ks[d * 65 + tx + 16];
            float b2 = Ks[d * 65 + tx + 32];
            float b3 = Ks[d * 65 + tx + 48];
            float a[8] = {a0.x, a0.y, a0.z, a0.w, a1.x, a1.y, a1.z, a1.w};
#pragma unroll
            for (int i = 0; i < 8; i++) {
                S[i][0] += a[i] * b0; S[i][1] += a[i] * b1;
                S[i][2] += a[i] * b2; S[i][3] += a[i] * b3;
            }
        }

        // Online softmax (row state uniform across the 16 tx lanes of a group)
        float corr[8];
#pragma unroll
        for (int i = 0; i < 8; i++) {
            float mi = fmaxf(fmaxf(S[i][0], S[i][1]), fmaxf(S[i][2], S[i][3]));
#pragma unroll
            for (int o = 8; o; o >>= 1) mi = fmaxf(mi, __shfl_xor_sync(~0u, mi, o, 16));
            float mn = fmaxf(mrow[i], mi);
            corr[i] = __expf(mrow[i] - mn);
            mrow[i] = mn;
            float ps = 0.f;
#pragma unroll
            for (int j = 0; j < 4; j++) {
                S[i][j] = __expf(S[i][j] - mn);
                ps += S[i][j];
            }
#pragma unroll
            for (int o = 8; o; o >>= 1) ps += __shfl_xor_sync(~0u, ps, o, 16);
            lrow[i] = lrow[i] * corr[i] + ps;
        }

        // Stage P (s-major) for PV
#pragma unroll
        for (int j = 0; j < 4; j++) {
            int s = tx + 16 * j;
            float4 p0 = make_float4(S[0][j], S[1][j], S[2][j], S[3][j]);
            float4 p1 = make_float4(S[4][j], S[5][j], S[6][j], S[7][j]);
            *(float4*)&Ps[s * 68 + r0] = p0;
            *(float4*)&Ps[s * 68 + r0 + 4] = p1;
        }
#pragma unroll
        for (int i = 0; i < 8; i++)
#pragma unroll
            for (int j = 0; j < 4; j++) acc[i][j] *= corr[i];
        __syncthreads();

        // O += P V   (O[r][d]: d = tx+16j; reduction index s warp-uniform)
#pragma unroll 4
        for (int s = 0; s < 64; s++) {
            float4 p0 = *(float4*)&Ps[s * 68 + r0];
            float4 p1 = *(float4*)&Ps[s * 68 + r0 + 4];
            float v0 = Vs[(tx + 0) * 65 + s];
            float v1 = Vs[(tx + 16) * 65 + s];
            float v2 = Vs[(tx + 32) * 65 + s];
            float v3 = Vs[(tx + 48) * 65 + s];
            float p[8] = {p0.x, p0.y, p0.z, p0.w, p1.x, p1.y, p1.z, p1.w};
#pragma unroll
            for (int i = 0; i < 8; i++) {
                acc[i][0] += p[i] * v0; acc[i][1] += p[i] * v1;
                acc[i][2] += p[i] * v2; acc[i][3] += p[i] * v3;
            }
        }
    }

    // Transpose output through smem so the [C,T] global write is coalesced.
    float inv[8];
#pragma unroll
    for (int i = 0; i < 8; i++) inv[i] = 1.f / lrow[i];
    __syncthreads();  // all PV reads of Ps done before reuse
#pragma unroll
    for (int j = 0; j < 4; j++) {
        int d = tx + 16 * j;
        float4 o0 = make_float4(acc[0][j] * inv[0], acc[1][j] * inv[1],
                                acc[2][j] * inv[2], acc[3][j] * inv[3]);
        float4 o1 = make_float4(acc[4][j] * inv[4], acc[5][j] * inv[5],
                                acc[6][j] * inv[6], acc[7][j] * inv[7]);
        *(float4*)&Ps[d * 68 + r0] = o0;
        *(float4*)&Ps[d * 68 + r0 + 4] = o1;
    }
    __syncthreads();
    float* op = g_att + ((size_t)b * CC + h * 64) * TT + t0;
    for (int i = tid; i < 1024; i += 128) {
        int d = i >> 4, r4 = (i & 15) * 4;
        *(float4*)(op + (size_t)d * TT + r4) = *(float4*)&Ps[d * 68 + r4];
    }
}

// ---------------------------------------------------------------------------
extern "C" void kernel_launch(void* const* d_in, const int* in_sizes, int n_in,
                              void* d_out, int out_size) {
    const float* x      = (const float*)d_in[0];
    const float* gamma  = (const float*)d_in[1];
    const float* beta   = (const float*)d_in[2];
    const float* w_qkv  = (const float*)d_in[3];
    const float* b_qkv  = (const float*)d_in[4];
    const float* w_proj = (const float*)d_in[5];
    const float* b_proj = (const float*)d_in[6];
    float* out = (float*)d_out;

    float *pqkv, *patt;
    cudaGetSymbolAddress((void**)&pqkv, g_qkv);
    cudaGetSymbolAddress((void**)&patt, g_att);

    // 1. GroupNorm statistics (normalization fused into QKV GEMM)
    gn_stats_kernel<<<BB * 32, 256>>>(x, gamma, beta);

    // 2. QKV projection: [1536,512] x [512,2048] per batch, GN fused on B-load
    gemm128<false, true><<<dim3(16, 12, BB), 256>>>(w_qkv, x, b_qkv, nullptr,
                                                    pqkv, 3 * CC, TT, CC);

    // 3. Flash attention (66.5 KB dynamic smem)
    const int ATTN_SMEM = (2 * 64 * 68 + 2 * 64 * 65) * (int)sizeof(float);
    cudaFuncSetAttribute(attn_kernel, cudaFuncAttributeMaxDynamicSharedMemorySize,
                         ATTN_SMEM);
    attn_kernel<<<dim3(TT / 64, BB * 8), 128, ATTN_SMEM>>>();

    // 4. Output projection + bias + residual
    gemm128<true, false><<<dim3(16, 4, BB), 256>>>(w_proj, patt, b_proj, x, out,
                                                   CC, TT, CC);
}

// round 7
// speedup vs baseline: 1.1803x; 1.1803x over previous
#include <cuda_runtime.h>
#include <math.h>

#define TT 2048
#define CC 512
#define BB 4

// Scratch (static device arrays — no allocation allowed)
__device__ float g_qkv[BB * 3 * CC * TT];  // qkv projections [B,3C,T]
__device__ float g_att[BB * CC * TT];      // attention output [B,C,T]
__device__ float g_scale[BB * CC];         // fused GN: per (b,c) scale
__device__ float g_shift[BB * CC];         // fused GN: per (b,c) shift

// ---- packed f32x2 helpers (SASS FFMA2 — only reachable via PTX) ------------
typedef unsigned long long u64;

__device__ __forceinline__ u64 pk2(float lo, float hi) {
    u64 r;
    asm("mov.b64 %0, {%1, %2};" : "=l"(r)
        : "r"(__float_as_uint(lo)), "r"(__float_as_uint(hi)));
    return r;
}
__device__ __forceinline__ u64 dup2(float v) { return pk2(v, v); }
__device__ __forceinline__ void fma2(u64& d, u64 a, u64 b) {
    asm("fma.rn.f32x2 %0, %1, %2, %0;" : "+l"(d) : "l"(a), "l"(b));
}
__device__ __forceinline__ void mul2(u64& d, u64 a) {
    asm("mul.rn.f32x2 %0, %0, %1;" : "+l"(d) : "l"(a));
}
__device__ __forceinline__ float2 upk(u64 v) {
    unsigned lo, hi;
    asm("mov.b64 {%0, %1}, %2;" : "=r"(lo), "=r"(hi) : "l"(v));
    return make_float2(__uint_as_float(lo), __uint_as_float(hi));
}

// ---------------------------------------------------------------------------
// GroupNorm statistics: one block per (batch, group). Emits per-channel
// affine (scale, shift) so normalization fuses into the QKV GEMM B-load.
// ---------------------------------------------------------------------------
__global__ void __launch_bounds__(256) gn_stats_kernel(const float* __restrict__ x,
                                                       const float* __restrict__ gamma,
                                                       const float* __restrict__ beta) {
    int bg = blockIdx.x;
    int b = bg >> 5, g = bg & 31;
    const float* xp = x + ((size_t)b * CC + g * 16) * TT;
    int tid = threadIdx.x;

    const int N4 = 16 * TT / 4;  // 8192 float4
    const float4* x4 = (const float4*)xp;
    float s = 0.f, s2 = 0.f;
    for (int i = tid; i < N4; i += 256) {
        float4 v = x4[i];
        s += v.x + v.y + v.z + v.w;
        s2 += v.x * v.x + v.y * v.y + v.z * v.z + v.w * v.w;
    }
#pragma unroll
    for (int o = 16; o; o >>= 1) {
        s += __shfl_xor_sync(~0u, s, o);
        s2 += __shfl_xor_sync(~0u, s2, o);
    }
    __shared__ float rs[8], rs2[8];
    __shared__ float smean, srinv;
    int w = tid >> 5;
    if ((tid & 31) == 0) { rs[w] = s; rs2[w] = s2; }
    __syncthreads();
    if (tid == 0) {
        float S = 0.f, S2 = 0.f;
        for (int i = 0; i < 8; i++) { S += rs[i]; S2 += rs2[i]; }
        const float invn = 1.f / (16.f * TT);
        float mean = S * invn;
        float var = S2 * invn - mean * mean;
        smean = mean;
        srinv = rsqrtf(var + 1e-5f);
    }
    __syncthreads();
    if (tid < 16) {
        int c = g * 16 + tid;
        float ga = gamma[c] * srinv;
        g_scale[b * CC + c] = ga;
        g_shift[b * CC + c] = beta[c] - smean * ga;
    }
}

// ---------------------------------------------------------------------------
// Tiled SGEMM with packed FFMA2: C[z] = A[M,K] * B[z][K,N] + bias[M] (+res).
// BM=BN=128, BK=16; 256 threads; 8x8 micro-tile. Accumulators are f32x2
// pairs along the column (N) axis: B column-pairs come free from LDS.128;
// A values are dup-packed (8 ALU movs per kk, hidden under the fma block).
// Software-pipelined global loads. GN=true applies per-channel affine to B.
// ---------------------------------------------------------------------------
template <bool RES, bool GN>
__global__ void __launch_bounds__(256, 2) gemm128(const float* __restrict__ A,
                                                  const float* __restrict__ Bm,
                                                  const float* __restrict__ bias,
                                                  const float* __restrict__ res,
                                                  float* __restrict__ Cm,
                                                  int M, int N, int K) {
    int z = blockIdx.z;
    Bm += (size_t)z * K * N;
    Cm += (size_t)z * M * N;
    if (RES) res += (size_t)z * M * N;
    int m0 = blockIdx.y * 128, n0 = blockIdx.x * 128;

    __shared__ float As[16][132];  // k-major transposed A tile (row = 528B)
    __shared__ float Bs[16][128];

    int tid = threadIdx.x;
    int tx = tid & 15, ty = tid >> 4;
    int ar = tid >> 2, akc = (tid & 3) * 4;      // A: rows ar, ar+64; k-chunk akc
    int brow = tid >> 5, bcol = (tid & 31) * 4;  // B: rows brow, brow+8

    const float* Ap0 = A + (size_t)(m0 + ar) * K + akc;
    const float* Ap1 = A + (size_t)(m0 + ar + 64) * K + akc;
    const float* Bp0 = Bm + (size_t)brow * N + n0 + bcol;
    const float* Bp1 = Bm + (size_t)(brow + 8) * N + n0 + bcol;

    u64 acc[8][4];
#pragma unroll
    for (int i = 0; i < 8; i++)
#pragma unroll
        for (int j = 0; j < 4; j++) acc[i][j] = 0ull;

    float4 a0, a1, b0, b1;
    a0 = *(const float4*)(Ap0);
    a1 = *(const float4*)(Ap1);
    b0 = *(const float4*)(Bp0);
    b1 = *(const float4*)(Bp1);
    if (GN) {
        float ga0 = g_scale[z * CC + brow], be0 = g_shift[z * CC + brow];
        float ga1 = g_scale[z * CC + brow + 8], be1 = g_shift[z * CC + brow + 8];
        b0.x = b0.x * ga0 + be0; b0.y = b0.y * ga0 + be0;
        b0.z = b0.z * ga0 + be0; b0.w = b0.w * ga0 + be0;
        b1.x = b1.x * ga1 + be1; b1.y = b1.y * ga1 + be1;
        b1.z = b1.z * ga1 + be1; b1.w = b1.w * ga1 + be1;
    }

    for (int k0 = 0; k0 < K; k0 += 16) {
        __syncthreads();
        As[akc + 0][ar] = a0.x; As[akc + 1][ar] = a0.y;
        As[akc + 2][ar] = a0.z; As[akc + 3][ar] = a0.w;
        As[akc + 0][ar + 64] = a1.x; As[akc + 1][ar + 64] = a1.y;
        As[akc + 2][ar + 64] = a1.z; As[akc + 3][ar + 64] = a1.w;
        *(float4*)&Bs[brow][bcol] = b0;
        *(float4*)&Bs[brow + 8][bcol] = b1;
        __syncthreads();

        // Prefetch next tile (hidden under the FFMA2 block)
        int kn = k0 + 16;
        if (kn < K) {
            a0 = *(const float4*)(Ap0 + kn);
            a1 = *(const float4*)(Ap1 + kn);
            b0 = *(const float4*)(Bp0 + (size_t)kn * N);
            b1 = *(const float4*)(Bp1 + (size_t)kn * N);
            if (GN) {
                float ga0 = g_scale[z * CC + kn + brow];
                float be0 = g_shift[z * CC + kn + brow];
                float ga1 = g_scale[z * CC + kn + brow + 8];
                float be1 = g_shift[z * CC + kn + brow + 8];
                b0.x = b0.x * ga0 + be0; b0.y = b0.y * ga0 + be0;
                b0.z = b0.z * ga0 + be0; b0.w = b0.w * ga0 + be0;
                b1.x = b1.x * ga1 + be1; b1.y = b1.y * ga1 + be1;
                b1.z = b1.z * ga1 + be1; b1.w = b1.w * ga1 + be1;
            }
        }

#pragma unroll
        for (int kk = 0; kk < 16; kk++) {
            float4 xa0 = *(float4*)&As[kk][ty * 8];
            float4 xa1 = *(float4*)&As[kk][ty * 8 + 4];
            ulonglong2 yb0 = *(ulonglong2*)&Bs[kk][tx * 8];      // cols (0,1),(2,3)
            ulonglong2 yb1 = *(ulonglong2*)&Bs[kk][tx * 8 + 4];  // cols (4,5),(6,7)
            float av[8] = {xa0.x, xa0.y, xa0.z, xa0.w, xa1.x, xa1.y, xa1.z, xa1.w};
#pragma unroll
            for (int i = 0; i < 8; i++) {
                u64 aa = dup2(av[i]);
                fma2(acc[i][0], aa, yb0.x);
                fma2(acc[i][1], aa, yb0.y);
                fma2(acc[i][2], aa, yb1.x);
                fma2(acc[i][3], aa, yb1.y);
            }
        }
    }

#pragma unroll
    for (int i = 0; i < 8; i++) {
        int m = m0 + ty * 8 + i;
        float bi = bias[m];
        float2 p0 = upk(acc[i][0]), p1 = upk(acc[i][1]);
        float2 p2 = upk(acc[i][2]), p3 = upk(acc[i][3]);
        float4 c0 = make_float4(p0.x + bi, p0.y + bi, p1.x + bi, p1.y + bi);
        float4 c1 = make_float4(p2.x + bi, p2.y + bi, p3.x + bi, p3.y + bi);
        size_t off = (size_t)m * N + n0 + tx * 8;
        if (RES) {
            float4 r0 = *(const float4*)(res + off);
            float4 r1 = *(const float4*)(res + off + 4);
            c0.x += r0.x; c0.y += r0.y; c0.z += r0.z; c0.w += r0.w;
            c1.x += r1.x; c1.y += r1.y; c1.z += r1.z; c1.w += r1.w;
        }
        *(float4*)(Cm + off) = c0;
        *(float4*)(Cm + off + 4) = c1;
    }
}

// ---------------------------------------------------------------------------
// Flash attention, fp32 with packed FFMA2. One block per (b,h, 64-query
// tile), 128 threads, 8x4 micro-tile. f32x2 pairs run along the ROW axis:
// Q/P float4 loads give free (r, r+1) pairs; K/V scalars are dup-packed.
// Ks/Vs row stride 66 (even) so staging can use aligned float2 LDG/STS;
// compute-phase loads remain conflict-free (checked per-phase).
// ---------------------------------------------------------------------------
__global__ void __launch_bounds__(128, 3) attn_kernel() {
    extern __shared__ float sm[];
    float* Qs = sm;                 // [64][68]  Qs[d*68 + r]
    float* Ps = sm + 64 * 68;       // [64][68]  Ps[s*68 + r]; reused as Os
    float* Ks = sm + 2 * 64 * 68;   // [64][66]  Ks[d*66 + s]
    float* Vs = Ks + 64 * 66;       // [64][66]  Vs[d*66 + s]

    int bh = blockIdx.y;
    int b = bh >> 3, h = bh & 7;
    int t0 = blockIdx.x * 64;
    const float* qp = g_qkv + ((size_t)b * 1536 + h * 192) * TT + t0;
    const float* kp = g_qkv + ((size_t)b * 1536 + h * 192 + 64) * TT;
    const float* vp = kp + (size_t)64 * TT;

    int tid = threadIdx.x;
    int tx = tid & 15, ty = tid >> 4;  // ty 0..7
    int r0 = ty * 8;

    // Q tile (float4 staging), pre-scaled by 1/sqrt(dh) = 0.125
    for (int i = tid; i < 1024; i += 128) {
        int d = i >> 4, r4 = (i & 15) * 4;
        float4 v = *(const float4*)(qp + (size_t)d * TT + r4);
        v.x *= 0.125f; v.y *= 0.125f; v.z *= 0.125f; v.w *= 0.125f;
        *(float4*)&Qs[d * 68 + r4] = v;
    }

    u64 acc2[4][4];  // row-pairs (2ip,2ip+1) x col j
#pragma unroll
    for (int ip = 0; ip < 4; ip++)
#pragma unroll
        for (int j = 0; j < 4; j++) acc2[ip][j] = 0ull;
    float mrow[8], lrow[8] = {};
#pragma unroll
    for (int i = 0; i < 8; i++) mrow[i] = -1e30f;

    for (int kt = 0; kt < 32; kt++) {
        const float* kpt = kp + kt * 64;
        const float* vpt = vp + kt * 64;
        __syncthreads();
        // float2 staging: 2048 float2 per tensor, 16 iter/thread each
        for (int i = tid; i < 2048; i += 128) {
            int d = i >> 5, s2 = (i & 31) * 2;
            *(float2*)&Ks[d * 66 + s2] = *(const float2*)(kpt + (size_t)d * TT + s2);
            *(float2*)&Vs[d * 66 + s2] = *(const float2*)(vpt + (size_t)d * TT + s2);
        }
        __syncthreads();

        // S = Q K^T  (row-pairs x 4 cols, FFMA2)
        u64 S2[4][4];
#pragma unroll
        for (int ip = 0; ip < 4; ip++)
#pragma unroll
            for (int j = 0; j < 4; j++) S2[ip][j] = 0ull;
#pragma unroll 4
        for (int d = 0; d < 64; d++) {
            ulonglong2 qa = *(ulonglong2*)&Qs[d * 68 + r0];      // rows (0,1),(2,3)
            ulonglong2 qb = *(ulonglong2*)&Qs[d * 68 + r0 + 4];  // rows (4,5),(6,7)
            u64 bb0 = dup2(Ks[d * 66 + tx]);
            u64 bb1 = dup2(Ks[d * 66 + tx + 16]);
            u64 bb2 = dup2(Ks[d * 66 + tx + 32]);
            u64 bb3 = dup2(Ks[d * 66 + tx + 48]);
            fma2(S2[0][0], qa.x, bb0); fma2(S2[0][1], qa.x, bb1);
            fma2(S2[0][2], qa.x, bb2); fma2(S2[0][3], qa.x, bb3);
            fma2(S2[1][0], qa.y, bb0); fma2(S2[1][1], qa.y, bb1);
            fma2(S2[1][2], qa.y, bb2); fma2(S2[1][3], qa.y, bb3);
            fma2(S2[2][0], qb.x, bb0); fma2(S2[2][1], qb.x, bb1);
            fma2(S2[2][2], qb.x, bb2); fma2(S2[2][3], qb.x, bb3);
            fma2(S2[3][0], qb.y, bb0); fma2(S2[3][1], qb.y, bb1);
            fma2(S2[3][2], qb.y, bb2); fma2(S2[3][3], qb.y, bb3);
        }

        // Unpack to per-row scalars for softmax
        float S[8][4];
#pragma unroll
        for (int ip = 0; ip < 4; ip++)
#pragma unroll
            for (int j = 0; j < 4; j++) {
                float2 v = upk(S2[ip][j]);
                S[2 * ip][j] = v.x;
                S[2 * ip + 1][j] = v.y;
            }

        // Online softmax (row state uniform across the 16 tx lanes)
        float corr[8];
#pragma unroll
        for (int i = 0; i < 8; i++) {
            float mi = fmaxf(fmaxf(S[i][0], S[i][1]), fmaxf(S[i][2], S[i][3]));
#pragma unroll
            for (int o = 8; o; o >>= 1) mi = fmaxf(mi, __shfl_xor_sync(~0u, mi, o, 16));
            float mn = fmaxf(mrow[i], mi);
            corr[i] = __expf(mrow[i] - mn);
            mrow[i] = mn;
            float ps = 0.f;
#pragma unroll
            for (int j = 0; j < 4; j++) {
                S[i][j] = __expf(S[i][j] - mn);
                ps += S[i][j];
            }
#pragma unroll
            for (int o = 8; o; o >>= 1) ps += __shfl_xor_sync(~0u, ps, o, 16);
            lrow[i] = lrow[i] * corr[i] + ps;
        }

        // Stage P (s-major) for PV
#pragma unroll
        for (int j = 0; j < 4; j++) {
            int s = tx + 16 * j;
            float4 p0 = make_float4(S[0][j], S[1][j], S[2][j], S[3][j]);
            float4 p1 = make_float4(S[4][j], S[5][j], S[6][j], S[7][j]);
            *(float4*)&Ps[s * 68 + r0] = p0;
            *(float4*)&Ps[s * 68 + r0 + 4] = p1;
        }
        // Rescale accumulators by row-pair correction
#pragma unroll
        for (int ip = 0; ip < 4; ip++) {
            u64 cp = pk2(corr[2 * ip], corr[2 * ip + 1]);
#pragma unroll
            for (int j = 0; j < 4; j++) mul2(acc2[ip][j], cp);
        }
        __syncthreads();

        // O += P V  (row-pairs x 4 d-cols, FFMA2)
#pragma unroll 4
        for (int s = 0; s < 64; s++) {
            ulonglong2 pa = *(ulonglong2*)&Ps[s * 68 + r0];
            ulonglong2 pb = *(ulonglong2*)&Ps[s * 68 + r0 + 4];
            u64 vv0 = dup2(Vs[(tx + 0) * 66 + s]);
            u64 vv1 = dup2(Vs[(tx + 16) * 66 + s]);
            u64 vv2 = dup2(Vs[(tx + 32) * 66 + s]);
            u64 vv3 = dup2(Vs[(tx + 48) * 66 + s]);
            fma2(acc2[0][0], pa.x, vv0); fma2(acc2[0][1], pa.x, vv1);
            fma2(acc2[0][2], pa.x, vv2); fma2(acc2[0][3], pa.x, vv3);
            fma2(acc2[1][0], pa.y, vv0); fma2(acc2[1][1], pa.y, vv1);
            fma2(acc2[1][2], pa.y, vv2); fma2(acc2[1][3], pa.y, vv3);
            fma2(acc2[2][0], pb.x, vv0); fma2(acc2[2][1], pb.x, vv1);
            fma2(acc2[2][2], pb.x, vv2); fma2(acc2[2][3], pb.x, vv3);
            fma2(acc2[3][0], pb.y, vv0); fma2(acc2[3][1], pb.y, vv1);
            fma2(acc2[3][2], pb.y, vv2); fma2(acc2[3][3], pb.y, vv3);
        }
    }

    // Unpack, normalize, transpose through smem for coalesced [C,T] write.
    float inv[8];
#pragma unroll
    for (int i = 0; i < 8; i++) inv[i] = 1.f / lrow[i];
    float accf[8][4];
#pragma unroll
    for (int ip = 0; ip < 4; ip++)
#pragma unroll
        for (int j = 0; j < 4; j++) {
            float2 v = upk(acc2[ip][j]);
            accf[2 * ip][j] = v.x * inv[2 * ip];
            accf[2 * ip + 1][j] = v.y * inv[2 * ip + 1];
        }
    __syncthreads();  // all PV reads of Ps done before reuse
#pragma unroll
    for (int j = 0; j < 4; j++) {
        int d = tx + 16 * j;
        float4 o0 = make_float4(accf[0][j], accf[1][j], accf[2][j], accf[3][j]);
        float4 o1 = make_float4(accf[4][j], accf[5][j], accf[6][j], accf[7][j]);
        *(float4*)&Ps[d * 68 + r0] = o0;
        *(float4*)&Ps[d * 68 + r0 + 4] = o1;
    }
    __syncthreads();
    float* op = g_att + ((size_t)b * CC + h * 64) * TT + t0;
    for (int i = tid; i < 1024; i += 128) {
        int d = i >> 4, r4 = (i & 15) * 4;
        *(float4*)(op + (size_t)d * TT + r4) = *(float4*)&Ps[d * 68 + r4];
    }
}

// ---------------------------------------------------------------------------
extern "C" void kernel_launch(void* const* d_in, const int* in_sizes, int n_in,
                              void* d_out, int out_size) {
    const float* x      = (const float*)d_in[0];
    const float* gamma  = (const float*)d_in[1];
    const float* beta   = (const float*)d_in[2];
    const float* w_qkv  = (const float*)d_in[3];
    const float* b_qkv  = (const float*)d_in[4];
    const float* w_proj = (const float*)d_in[5];
    const float* b_proj = (const float*)d_in[6];
    float* out = (float*)d_out;

    float *pqkv, *patt;
    cudaGetSymbolAddress((void**)&pqkv, g_qkv);
    cudaGetSymbolAddress((void**)&patt, g_att);

    // 1. GroupNorm statistics (normalization fused into QKV GEMM)
    gn_stats_kernel<<<BB * 32, 256>>>(x, gamma, beta);

    // 2. QKV projection: [1536,512] x [512,2048] per batch, GN fused on B-load
    gemm128<false, true><<<dim3(16, 12, BB), 256>>>(w_qkv, x, b_qkv, nullptr,
                                                    pqkv, 3 * CC, TT, CC);

    // 3. Flash attention (67.6 KB dynamic smem)
    const int ATTN_SMEM = (2 * 64 * 68 + 2 * 64 * 66) * (int)sizeof(float);
    cudaFuncSetAttribute(attn_kernel, cudaFuncAttributeMaxDynamicSharedMemorySize,
                         ATTN_SMEM);
    attn_kernel<<<dim3(TT / 64, BB * 8), 128, ATTN_SMEM>>>();

    // 4. Output projection + bias + residual
    gemm128<true, false><<<dim3(16, 4, BB), 256>>>(w_proj, patt, b_proj, x, out,
                                                   CC, TT, CC);
}